// round 3
// baseline (speedup 1.0000x reference)
#include <cuda_runtime.h>
#include <cuda_bf16.h>
#include <math.h>

// Problem constants
#define BB   128
#define NN0  64
#define DD0  32
#define NN1  64
#define DD1  32
#define CC   2048      // N1*D1
#define KC   65        // conv kernel size

// -------- scratch (device globals; no allocation in kernel_launch) --------
__device__ float g_Wt[NN0 * DD0 * CC];          // [j][i][kz]           16 MB
__device__ float g_wt[NN1 * DD1 * DD1 * KC];    // [g][ci][ol][k]       17 MB
__device__ float g_U1[BB * NN0 * CC];           // [b][j][kz]           64 MB
__device__ float g_U2[BB * NN0 * CC];
__device__ float g_U3[BB * NN0 * CC];
__device__ float g_R1[BB * CC];
__device__ float g_R2[BB * CC];
__device__ float g_R3[BB * CC];
__device__ float g_Z [BB * CC];
__device__ float g_KV[BB * NN0 * NN0];          // [b][c][d]
__device__ float g_Xm[BB * NN0 * CC];           // [b][d][kz]           64 MB
__device__ float g_Sb[BB * CC * KC];            // [b][ch][k]           65 MB
__device__ float g_Pre[BB * CC];

__device__ __forceinline__ float focus_v3(float u) {
    float v = (fmaxf(u, 0.0f) + 1e-6f) * 0.2f;
    return v * v * v;
}

// -------- K0a: W[k][j][i][z] -> Wt[j][i][kz] --------
__global__ void k_transposeW(const float* __restrict__ W) {
    int tid = blockIdx.x * 256 + threadIdx.x;       // 4,194,304 total
    int kz   = tid & 2047;
    int rest = tid >> 11;
    int i = rest & 31;
    int j = rest >> 5;
    int k = kz >> 5;
    int z = kz & 31;
    g_Wt[tid] = W[k * 65536 + j * 1024 + i * 32 + z];
}

// -------- K0b: conv_w[o][ci][k] -> wt[g][ci][ol][k] --------
__global__ void k_transposeCW(const float* __restrict__ cw) {
    int tid = blockIdx.x * 256 + threadIdx.x;       // 4,259,840 total
    int k  = tid % 65;
    int r  = tid / 65;
    int ol = r & 31;
    int r2 = r >> 5;
    int ci = r2 & 31;
    int g  = r2 >> 5;
    g_wt[tid] = cw[(g * 32 + ol) * 2080 + ci * 65 + k];
}

// -------- K1: transform (all 3 inputs) --------
// grid (16 kz-tiles, 64 j), block 128. Each thread owns one kz, keeps 32 W in regs,
// loops all 128 batches from smem. W read once total.
__global__ __launch_bounds__(128) void k_transform(
    const float* __restrict__ x1, const float* __restrict__ x2, const float* __restrict__ x3)
{
    __shared__ float xs[3][128][32];   // 48KB
    int t  = threadIdx.x;
    int j  = blockIdx.y;
    int kz = blockIdx.x * 128 + t;

    for (int e = t; e < 128 * 32; e += 128) {
        int b = e >> 5, i = e & 31;
        int src = b * 2048 + j * 32 + i;
        xs[0][b][i] = x1[src];
        xs[1][b][i] = x2[src];
        xs[2][b][i] = x3[src];
    }

    float w[32];
    int wbase = (j * 32) * 2048 + kz;
#pragma unroll
    for (int ii = 0; ii < 32; ii++) w[ii] = g_Wt[wbase + ii * 2048];

    __syncthreads();

    for (int b = 0; b < 128; b++) {
        float a1 = 0.f, a2 = 0.f, a3 = 0.f;
#pragma unroll
        for (int ii = 0; ii < 32; ii++) {
            a1 = fmaf(w[ii], xs[0][b][ii], a1);
            a2 = fmaf(w[ii], xs[1][b][ii], a2);
            a3 = fmaf(w[ii], xs[2][b][ii], a3);
        }
        int o = b * 131072 + j * 2048 + kz;
        g_U1[o] = a1;
        g_U2[o] = a2;
        g_U3[o] = a3;
    }
}

// -------- K2: focus scale factors r = ||v|| / ||v^3|| per (b,kz) --------
__global__ void k_rnorm() {
    int tid = blockIdx.x * 256 + threadIdx.x;   // BB*CC threads
    int b  = tid >> 11;
    int kz = tid & 2047;
    int base = b * 131072 + kz;

    float s2a = 0.f, s6a = 0.f, s2b = 0.f, s6b = 0.f, s2c = 0.f, s6c = 0.f;
    for (int j = 0; j < 64; j++) {
        int idx = base + j * 2048;
        float v1 = (fmaxf(g_U1[idx], 0.f) + 1e-6f) * 0.2f;
        float v2 = (fmaxf(g_U2[idx], 0.f) + 1e-6f) * 0.2f;
        float v3 = (fmaxf(g_U3[idx], 0.f) + 1e-6f) * 0.2f;
        s2a += v1 * v1; float c1 = v1 * v1 * v1; s6a += c1 * c1;
        s2b += v2 * v2; float c2 = v2 * v2 * v2; s6b += c2 * c2;
        s2c += v3 * v3; float c3 = v3 * v3 * v3; s6c += c3 * c3;
    }
    g_R1[tid] = sqrtf(s2a) / sqrtf(s6a);
    g_R2[tid] = sqrtf(s2b) / sqrtf(s6b);
    g_R3[tid] = sqrtf(s2c) / sqrtf(s6c);
}

// -------- K3: s[b][j] then z[b][kz] --------
__global__ void k_z() {
    __shared__ float ss[64];
    int b = blockIdx.x;
    int t = threadIdx.x;
    int w = t >> 5, lane = t & 31;

    // pass 1: s[j] = sum_kz f1(u1[b][j][kz])
    for (int jj = 0; jj < 8; jj++) {
        int j = w * 8 + jj;
        float acc = 0.f;
        for (int kk = 0; kk < 64; kk++) {
            int kz = lane + kk * 32;
            float f = g_R1[b * 2048 + kz] * focus_v3(g_U1[b * 131072 + j * 2048 + kz]);
            acc += f;
        }
#pragma unroll
        for (int off = 16; off > 0; off >>= 1)
            acc += __shfl_down_sync(0xffffffff, acc, off);
        if (lane == 0) ss[j] = acc;
    }
    __syncthreads();

    // pass 2: z[kz] = 1/(sum_j f1 * s[j] + eps)
    for (int rep = 0; rep < 8; rep++) {
        int kz = t + rep * 256;
        float r1 = g_R1[b * 2048 + kz];
        float acc = 0.f;
        for (int j = 0; j < 64; j++) {
            float f = r1 * focus_v3(g_U1[b * 131072 + j * 2048 + kz]);
            acc = fmaf(f, ss[j], acc);
        }
        g_Z[b * 2048 + kz] = 1.0f / (acc + 1.1920929e-07f);
    }
}

// -------- K4: kv[b][c][d] = sum_kz f2(u2[b][c][kz]) * f3(u3[b][d][kz]) --------
__global__ void k_kv() {
    __shared__ float As[64][33];
    __shared__ float Bs[64][33];
    int b = blockIdx.x;
    int t = threadIdx.x;
    int c0 = (t & 15) * 4;
    int d0 = (t >> 4) * 4;

    float acc[4][4];
#pragma unroll
    for (int i = 0; i < 4; i++)
#pragma unroll
        for (int jd = 0; jd < 4; jd++) acc[i][jd] = 0.f;

    for (int ch = 0; ch < 64; ch++) {
        int kz0 = ch * 32;
        for (int e = t; e < 2048; e += 256) {
            int c = e >> 5, kk = e & 31;
            int kz = kz0 + kk;
            float r2 = g_R2[b * 2048 + kz];
            float r3 = g_R3[b * 2048 + kz];
            As[c][kk] = r2 * focus_v3(g_U2[b * 131072 + c * 2048 + kz]);
            Bs[c][kk] = r3 * focus_v3(g_U3[b * 131072 + c * 2048 + kz]);
        }
        __syncthreads();
#pragma unroll 4
        for (int kk = 0; kk < 32; kk++) {
            float av[4], bv[4];
#pragma unroll
            for (int i = 0; i < 4; i++) { av[i] = As[c0 + i][kk]; bv[i] = Bs[d0 + i][kk]; }
#pragma unroll
            for (int i = 0; i < 4; i++)
#pragma unroll
                for (int jd = 0; jd < 4; jd++)
                    acc[i][jd] = fmaf(av[i], bv[jd], acc[i][jd]);
        }
        __syncthreads();
    }
#pragma unroll
    for (int i = 0; i < 4; i++)
#pragma unroll
        for (int jd = 0; jd < 4; jd++)
            g_KV[b * 4096 + (c0 + i) * 64 + (d0 + jd)] = acc[i][jd];
}

// -------- K5: Xm[b][d][kz] = z[b][kz] * sum_c f1(u1[b][c][kz]) * kv[b][c][d] --------
__global__ __launch_bounds__(128) void k_xmid() {
    __shared__ __align__(16) float kvs[4096];
    int b = blockIdx.y;
    int t = threadIdx.x;
    int kz = blockIdx.x * 128 + t;

    for (int e = t; e < 4096; e += 128) kvs[e] = g_KV[b * 4096 + e];
    __syncthreads();

    float xr[64];
#pragma unroll
    for (int d = 0; d < 64; d++) xr[d] = 0.f;

    float r1 = g_R1[b * 2048 + kz];
    for (int c = 0; c < 64; c++) {
        float f = r1 * focus_v3(g_U1[b * 131072 + c * 2048 + kz]);
        const float4* kvp = reinterpret_cast<const float4*>(&kvs[c * 64]);
#pragma unroll
        for (int d4 = 0; d4 < 16; d4++) {
            float4 kq = kvp[d4];
            xr[4 * d4 + 0] = fmaf(f, kq.x, xr[4 * d4 + 0]);
            xr[4 * d4 + 1] = fmaf(f, kq.y, xr[4 * d4 + 1]);
            xr[4 * d4 + 2] = fmaf(f, kq.z, xr[4 * d4 + 2]);
            xr[4 * d4 + 3] = fmaf(f, kq.w, xr[4 * d4 + 3]);
        }
    }
    float zv = g_Z[b * 2048 + kz];
#pragma unroll
    for (int d = 0; d < 64; d++)
        g_Xm[b * 131072 + d * 2048 + kz] = zv * xr[d];
}

// -------- K6a: window sums S[b][ch][k] from prefix sums of Xm along positions --------
__global__ void k_prefix() {
    __shared__ float T [64][65];
    __shared__ float Ps[65][64];
    int b = blockIdx.y;
    int ch0 = blockIdx.x * 64;
    int t = threadIdx.x;

    for (int e = t; e < 4096; e += 256) {
        int d = e >> 6, cc = e & 63;
        T[d][cc] = g_Xm[b * 131072 + d * 2048 + ch0 + cc];
    }
    __syncthreads();
    if (t < 64) {
        float run = 0.f;
        Ps[0][t] = 0.f;
        for (int d = 0; d < 64; d++) { run += T[d][t]; Ps[d + 1][t] = run; }
    }
    __syncthreads();
    for (int e = t; e < 64 * 65; e += 256) {
        int cc = e / 65, k = e % 65;
        int hi = min(64, k + 32);
        int lo = max(0, k - 32);
        g_Sb[b * 133120 + (ch0 + cc) * 65 + k] = Ps[hi][cc] - Ps[lo][cc];
    }
}

// -------- K6b: conv-as-GEMM  pre[b][o] = sum_{ci,k} w*S + 64*bias + sum_t x --------
__global__ __launch_bounds__(256) void k_conv(const float* __restrict__ conv_b) {
    __shared__ __align__(16) float ws[32 * 68];   // [ol][k]
    __shared__ __align__(16) float Ss[32 * 68];   // [bb][k]
    int t  = threadIdx.x;
    int o  = t & 31;
    int bg = t >> 5;             // 0..7, 4 batches each
    int b0 = blockIdx.x * 32;
    int g  = blockIdx.y;

    float acc[4] = {0.f, 0.f, 0.f, 0.f};

    for (int ci = 0; ci < 32; ci++) {
        int base_w  = (g * 32 + ci) * 2080;
        int base_sb = (g * 32 + ci) * 65;
        for (int e = t; e < 2080; e += 256) {
            int ol = e / 65, k = e % 65;
            ws[ol * 68 + k] = g_wt[base_w + e];
            int bb = ol;  // reuse decomposition: e = bb*65 + k as well
            Ss[bb * 68 + k] = g_Sb[(b0 + bb) * 133120 + base_sb + k];
        }
        __syncthreads();

        const float4* wp = reinterpret_cast<const float4*>(ws + o * 68);
#pragma unroll
        for (int k4 = 0; k4 < 16; k4++) {
            float4 wv = wp[k4];
#pragma unroll
            for (int jb = 0; jb < 4; jb++) {
                const float4 sv = *reinterpret_cast<const float4*>(Ss + (bg * 4 + jb) * 68 + k4 * 4);
                acc[jb] = fmaf(wv.x, sv.x, fmaf(wv.y, sv.y, fmaf(wv.z, sv.z, fmaf(wv.w, sv.w, acc[jb]))));
            }
        }
        float wl = ws[o * 68 + 64];
#pragma unroll
        for (int jb = 0; jb < 4; jb++)
            acc[jb] = fmaf(wl, Ss[(bg * 4 + jb) * 68 + 64], acc[jb]);
        __syncthreads();
    }

    int og = g * 32 + o;
    float bias = 64.0f * conv_b[og];
#pragma unroll
    for (int jb = 0; jb < 4; jb++) {
        int b = b0 + bg * 4 + jb;
        float sumx = g_Sb[b * 133120 + og * 65 + 32];   // full-row sum
        g_Pre[b * 2048 + og] = acc[jb] + bias + sumx;
    }
}

// -------- K7: squash over D1=32 per (b, n1) --------
__global__ void k_squash(float* __restrict__ out) {
    int t = threadIdx.x;
    int gid = blockIdx.x * 8 + (t >> 5);   // warp id: 0..8191
    int lane = t & 31;
    int b = gid >> 6;
    int n = gid & 63;
    int idx = b * 2048 + n * 32 + lane;
    float val = g_Pre[idx];
    float sq = val * val;
#pragma unroll
    for (int off = 16; off > 0; off >>= 1)
        sq += __shfl_xor_sync(0xffffffff, sq, off);
    float norm = sqrtf(sq);
    float coef = 1.0f - 1.0f / (expf(norm) + 1e-20f);
    out[idx] = coef * val / (norm + 1e-20f);
}

extern "C" void kernel_launch(void* const* d_in, const int* in_sizes, int n_in,
                              void* d_out, int out_size) {
    const float* x1     = (const float*)d_in[0];
    const float* x2     = (const float*)d_in[1];
    const float* x3     = (const float*)d_in[2];
    const float* W      = (const float*)d_in[3];
    const float* conv_w = (const float*)d_in[4];
    const float* conv_b = (const float*)d_in[5];
    float* out = (float*)d_out;

    k_transposeW <<<4194304 / 256, 256>>>(W);
    k_transposeCW<<<4259840 / 256, 256>>>(conv_w);
    k_transform  <<<dim3(16, 64), 128>>>(x1, x2, x3);
    k_rnorm      <<<(BB * CC) / 256, 256>>>();
    k_z          <<<BB, 256>>>();
    k_kv         <<<BB, 256>>>();
    k_xmid       <<<dim3(16, BB), 128>>>();
    k_prefix     <<<dim3(32, BB), 256>>>();
    k_conv       <<<dim3(4, 64), 256>>>(conv_b);
    k_squash     <<<1024, 256>>>(out);
}

// round 5
// speedup vs baseline: 1.2396x; 1.2396x over previous
#include <cuda_runtime.h>
#include <math.h>

typedef unsigned long long ull;

// Problem constants
#define BB   128
#define NN0  64      // positions (j / c / d)
#define DD0  32      // i
#define CC   2048    // channels kz = n1*32 + d1
#define KC   65

// -------- scratch (device globals) --------
__device__ float g_Wt[NN0 * DD0 * CC];          // [j][i][kz]
__device__ float g_A [CC * DD0 * NN0];          // A'[o][ci][d]
__device__ float g_U1[BB * NN0 * CC];           // [b][j][kz]
__device__ float g_U2[BB * NN0 * CC];
__device__ float g_U3[BB * NN0 * CC];
__device__ float g_R1[BB * CC];
__device__ float g_R2[BB * CC];
__device__ float g_R3[BB * CC];
__device__ float g_Spart[BB * NN0 * 32];        // per-warp partials of s[b][j]
__device__ float g_KVh[2 * BB * NN0 * NN0];     // split-k kv partials [h][b][c][d]
__device__ float g_Xm[BB * CC * NN0];           // [b][kz][d]  (d contiguous)
__device__ float g_Pre[BB * CC];

// -------- f32x2 helpers --------
__device__ __forceinline__ ull pk2(float lo, float hi) {
    ull r; asm("mov.b64 %0, {%1, %2};" : "=l"(r) : "f"(lo), "f"(hi)); return r;
}
__device__ __forceinline__ void upk2(float& lo, float& hi, ull v) {
    asm("mov.b64 {%0, %1}, %2;" : "=f"(lo), "=f"(hi) : "l"(v));
}
__device__ __forceinline__ void fma2(ull& acc, ull a, ull b) {
    asm("fma.rn.f32x2 %0, %1, %2, %3;" : "=l"(acc) : "l"(a), "l"(b), "l"(acc));
}
__device__ __forceinline__ ull add2(ull a, ull b) {
    ull r; asm("add.rn.f32x2 %0, %1, %2;" : "=l"(r) : "l"(a), "l"(b)); return r;
}

__device__ __forceinline__ float focus_v(float u) {
    return fmaf(fmaxf(u, 0.0f), 0.2f, 2e-7f);   // (relu(u)+1e-6)/5
}

// -------- K0a: W[k][j][i][z] -> Wt[j][i][kz] --------
__global__ void k_transposeW(const float* __restrict__ W) {
    int tid = blockIdx.x * 256 + threadIdx.x;
    int kz   = tid & 2047;
    int rest = tid >> 11;
    int i = rest & 31;
    int j = rest >> 5;
    int k = kz >> 5;
    int z = kz & 31;
    g_Wt[tid] = W[k * 65536 + j * 1024 + i * 32 + z];
}

// -------- K0b: A'[o][ci][d] = window-sum of conv_w + identity --------
__global__ void k_prepA(const float* __restrict__ cw) {
    int tid = blockIdx.x * 256 + threadIdx.x;   // 65536
    int o = tid >> 5, ci = tid & 31;
    const float* wr = cw + (o * 32 + ci) * 65;
    float id = (ci == (o & 31)) ? 1.0f : 0.0f;
    float* ar = g_A + (o * 32 + ci) * 64;
    float s = 0.f;
    for (int k = 0; k <= 32; k++) s += wr[k];
    ar[0] = s + id;
    for (int p = 1; p < 64; p++) {
        int addk = p + 32;
        if (addk <= 64) s += wr[addk];
        int rmk = p - 32;
        if (rmk >= 0) s -= wr[rmk];
        ar[p] = s + id;
    }
}

// -------- K1: transform, f32x2 paired over batch --------
__global__ __launch_bounds__(128) void k_transform(
    const float* __restrict__ x1, const float* __restrict__ x2, const float* __restrict__ x3)
{
    __shared__ __align__(16) ull xs[3][64][32];   // b-pairs, 48KB
    int t  = threadIdx.x;
    int j  = blockIdx.y;
    int kz = blockIdx.x * 128 + t;

    for (int e = t; e < 64 * 32; e += 128) {
        int bp = e >> 5, i = e & 31;
        int s0 = (2 * bp) * 2048 + j * 32 + i, s1 = s0 + 2048;
        xs[0][bp][i] = pk2(x1[s0], x1[s1]);
        xs[1][bp][i] = pk2(x2[s0], x2[s1]);
        xs[2][bp][i] = pk2(x3[s0], x3[s1]);
    }

    ull w2[32];
    int wb = (j * 32) * 2048 + kz;
#pragma unroll
    for (int i = 0; i < 32; i++) { float w = g_Wt[wb + i * 2048]; w2[i] = pk2(w, w); }

    __syncthreads();

    for (int bp = 0; bp < 64; bp++) {
        ull a1 = 0ULL, a2 = 0ULL, a3 = 0ULL;
        const ulonglong2* p0 = (const ulonglong2*)xs[0][bp];
        const ulonglong2* p1 = (const ulonglong2*)xs[1][bp];
        const ulonglong2* p2 = (const ulonglong2*)xs[2][bp];
#pragma unroll
        for (int q = 0; q < 16; q++) {
            ulonglong2 v0 = p0[q], v1 = p1[q], v2 = p2[q];
            fma2(a1, w2[2 * q], v0.x); fma2(a1, w2[2 * q + 1], v0.y);
            fma2(a2, w2[2 * q], v1.x); fma2(a2, w2[2 * q + 1], v1.y);
            fma2(a3, w2[2 * q], v2.x); fma2(a3, w2[2 * q + 1], v2.y);
        }
        float lo, hi;
        int o0 = (2 * bp) * 131072 + j * 2048 + kz, o1 = o0 + 131072;
        upk2(lo, hi, a1); g_U1[o0] = lo; g_U1[o1] = hi;
        upk2(lo, hi, a2); g_U2[o0] = lo; g_U2[o1] = hi;
        upk2(lo, hi, a3); g_U3[o0] = lo; g_U3[o1] = hi;
    }
}

// -------- K2: focus ratios r = ||v||/||v^3|| + s[b][j] per-warp partials --------
__global__ __launch_bounds__(256) void k_rnorm() {
    int tid = blockIdx.x * 256 + threadIdx.x;   // 131072 threads, 2 kz each
    int b   = tid >> 10;
    int kz2 = tid & 1023;
    int base = b * 131072 + kz2 * 2;
    int lane = threadIdx.x & 31;
    int widx = (tid >> 5) & 31;                 // per-b warp index (32 per b)

    float s2ax=0,s6ax=0,s2ay=0,s6ay=0;
    float s2bx=0,s6bx=0,s2by=0,s6by=0;
    float s2cx=0,s6cx=0,s2cy=0,s6cy=0;
    for (int j = 0; j < 64; j++) {
        float2 q1 = *(const float2*)&g_U1[base + j * 2048];
        float2 q2 = *(const float2*)&g_U2[base + j * 2048];
        float2 q3 = *(const float2*)&g_U3[base + j * 2048];
        float v;
        v = focus_v(q1.x); { float v2=v*v, c=v2*v; s2ax+=v2; s6ax=fmaf(c,c,s6ax); }
        v = focus_v(q1.y); { float v2=v*v, c=v2*v; s2ay+=v2; s6ay=fmaf(c,c,s6ay); }
        v = focus_v(q2.x); { float v2=v*v, c=v2*v; s2bx+=v2; s6bx=fmaf(c,c,s6bx); }
        v = focus_v(q2.y); { float v2=v*v, c=v2*v; s2by+=v2; s6by=fmaf(c,c,s6by); }
        v = focus_v(q3.x); { float v2=v*v, c=v2*v; s2cx+=v2; s6cx=fmaf(c,c,s6cx); }
        v = focus_v(q3.y); { float v2=v*v, c=v2*v; s2cy+=v2; s6cy=fmaf(c,c,s6cy); }
    }
    float r1x = sqrtf(s2ax) * rsqrtf(s6ax), r1y = sqrtf(s2ay) * rsqrtf(s6ay);
    float r2x = sqrtf(s2bx) * rsqrtf(s6bx), r2y = sqrtf(s2by) * rsqrtf(s6by);
    float r3x = sqrtf(s2cx) * rsqrtf(s6cx), r3y = sqrtf(s2cy) * rsqrtf(s6cy);
    *(float2*)&g_R1[b * 2048 + kz2 * 2] = make_float2(r1x, r1y);
    *(float2*)&g_R2[b * 2048 + kz2 * 2] = make_float2(r2x, r2y);
    *(float2*)&g_R3[b * 2048 + kz2 * 2] = make_float2(r3x, r3y);

    // s partials: s[b][j] contribution of this warp's 64 kz (channels)
    for (int j = 0; j < 64; j++) {
        float2 q1 = *(const float2*)&g_U1[base + j * 2048];
        float vx = focus_v(q1.x), vy = focus_v(q1.y);
        float f = r1x * vx * vx * vx + r1y * vy * vy * vy;
#pragma unroll
        for (int off = 16; off > 0; off >>= 1)
            f += __shfl_xor_sync(0xffffffffu, f, off);
        if (lane == 0) g_Spart[b * 2048 + j * 32 + widx] = f;
    }
}

// -------- K3: kv split over channel halves, f32x2 paired over d --------
__global__ __launch_bounds__(256) void k_kv() {
    __shared__ __align__(16) float As2[32 * 68];    // [kk][c]
    __shared__ __align__(16) float Bs2[32 * 68];
    __shared__ float Rs2[1024], Rs3[1024];
    int h = blockIdx.x, b = blockIdx.y;
    int t = threadIdx.x;
    int c0 = (t & 15) * 4, d0 = (t >> 4) * 4;
    int kzbase = h * 1024;

    for (int e = t; e < 1024; e += 256) {
        Rs2[e] = g_R2[b * 2048 + kzbase + e];
        Rs3[e] = g_R3[b * 2048 + kzbase + e];
    }
    __syncthreads();

    ull acc[4][2];
#pragma unroll
    for (int i = 0; i < 4; i++) { acc[i][0] = 0ULL; acc[i][1] = 0ULL; }

    for (int ch = 0; ch < 32; ch++) {
        int kz0 = kzbase + ch * 32;
        for (int e = t; e < 2048; e += 256) {
            int c = e >> 5, kk = e & 31;
            int kz = kz0 + kk;
            float v2 = focus_v(g_U2[b * 131072 + c * 2048 + kz]);
            float v3 = focus_v(g_U3[b * 131072 + c * 2048 + kz]);
            As2[kk * 68 + c] = Rs2[ch * 32 + kk] * v2 * v2 * v2;
            Bs2[kk * 68 + c] = Rs3[ch * 32 + kk] * v3 * v3 * v3;
        }
        __syncthreads();
#pragma unroll
        for (int kk = 0; kk < 32; kk++) {
            float4 av = *(const float4*)&As2[kk * 68 + c0];
            ulonglong2 bv = *(const ulonglong2*)&Bs2[kk * 68 + d0];
            ull a0 = pk2(av.x, av.x), a1 = pk2(av.y, av.y);
            ull a2 = pk2(av.z, av.z), a3 = pk2(av.w, av.w);
            fma2(acc[0][0], a0, bv.x); fma2(acc[0][1], a0, bv.y);
            fma2(acc[1][0], a1, bv.x); fma2(acc[1][1], a1, bv.y);
            fma2(acc[2][0], a2, bv.x); fma2(acc[2][1], a2, bv.y);
            fma2(acc[3][0], a3, bv.x); fma2(acc[3][1], a3, bv.y);
        }
        __syncthreads();
    }
#pragma unroll
    for (int i = 0; i < 4; i++) {
        float l0, h0, l1, h1;
        upk2(l0, h0, acc[i][0]);
        upk2(l1, h1, acc[i][1]);
        int obase = (h * 128 + b) * 4096 + (c0 + i) * 64 + d0;
        g_KVh[obase + 0] = l0; g_KVh[obase + 1] = h0;
        g_KVh[obase + 2] = l1; g_KVh[obase + 3] = h1;
    }
}

// -------- K4: xmid with fused z; output [b][kz][d] via smem transpose --------
__global__ __launch_bounds__(128) void k_xmid() {
    __shared__ __align__(16) ull kvs2[2048];        // kv[c][d-pairs], 16KB
    __shared__ float spart[2048];
    __shared__ float ss[64];
    __shared__ float stage[64 * 65];    // half-tile transpose staging
    int b = blockIdx.y;
    int t = threadIdx.x;
    int kz = blockIdx.x * 128 + t;

    for (int e = t; e < 2048; e += 128) {
        ull p = ((const ull*)g_KVh)[b * 2048 + e];
        ull q = ((const ull*)g_KVh)[(128 + b) * 2048 + e];
        kvs2[e] = add2(p, q);
        spart[e] = g_Spart[b * 2048 + e];
    }
    __syncthreads();
    if (t < 64) {
        float s = 0.f;
        for (int w = 0; w < 32; w++) s += spart[t * 32 + w];
        ss[t] = s;
    }
    __syncthreads();

    ull xr[32];
#pragma unroll
    for (int d = 0; d < 32; d++) xr[d] = 0ULL;

    float r1 = g_R1[b * 2048 + kz];
    float zacc = 0.f;
    for (int c = 0; c < 64; c++) {
        float v = focus_v(g_U1[b * 131072 + c * 2048 + kz]);
        float f = r1 * v * v * v;
        zacc = fmaf(f, ss[c], zacc);
        ull f2v = pk2(f, f);
        const ulonglong2* kp = (const ulonglong2*)&kvs2[c * 32];
#pragma unroll
        for (int d8 = 0; d8 < 16; d8++) {
            ulonglong2 kq = kp[d8];
            fma2(xr[2 * d8],     f2v, kq.x);
            fma2(xr[2 * d8 + 1], f2v, kq.y);
        }
    }
    float z = 1.0f / (zacc + 1.1920929e-07f);

#pragma unroll
    for (int half = 0; half < 2; half++) {
        if ((t >> 6) == half) {
            int row = t & 63;
#pragma unroll
            for (int d2 = 0; d2 < 32; d2++) {
                float lo, hi; upk2(lo, hi, xr[d2]);
                stage[row * 65 + 2 * d2]     = lo * z;
                stage[row * 65 + 2 * d2 + 1] = hi * z;
            }
        }
        __syncthreads();
        for (int e = t; e < 4096; e += 128) {
            int kzi = e >> 6, d = e & 63;
            g_Xm[b * 131072 + (blockIdx.x * 128 + half * 64 + kzi) * 64 + d] = stage[kzi * 65 + d];
        }
        __syncthreads();
    }
}

// -------- K5: conv-as-GEMM with A'  pre[b][o] = sum_{ci,d} A'[o,ci,d]*x[b,c,d] + 64*bias --------
__global__ __launch_bounds__(256) void k_conv(const float* __restrict__ conv_b) {
    __shared__ __align__(16) float As[32 * 68];   // [ol][d]
    __shared__ __align__(16) float Xs[32 * 68];   // [bb][d]
    int t  = threadIdx.x;
    int o  = t & 31;
    int bg = t >> 5;
    int b0 = blockIdx.x * 32;
    int g  = blockIdx.y;

    ull acc[4] = {0ULL, 0ULL, 0ULL, 0ULL};

    for (int ci = 0; ci < 32; ci++) {
        for (int e = t; e < 2048; e += 256) {
            int ol = e >> 6, d = e & 63;
            As[ol * 68 + d] = g_A[((g * 32 + ol) * 32 + ci) * 64 + d];
            Xs[ol * 68 + d] = g_Xm[(b0 + ol) * 131072 + (g * 32 + ci) * 64 + d];
        }
        __syncthreads();
        const ulonglong2* ap = (const ulonglong2*)&As[o * 68];
#pragma unroll
        for (int k8 = 0; k8 < 16; k8++) {
            ulonglong2 av = ap[k8];           // 4 floats of A'[o][.]
#pragma unroll
            for (int jb = 0; jb < 4; jb++) {
                ulonglong2 xv = *(const ulonglong2*)&Xs[(bg * 4 + jb) * 68 + k8 * 4];
                fma2(acc[jb], av.x, xv.x);
                fma2(acc[jb], av.y, xv.y);
            }
        }
        __syncthreads();
    }

    int og = g * 32 + o;
    float bias = 64.0f * conv_b[og];
#pragma unroll
    for (int jb = 0; jb < 4; jb++) {
        float lo, hi; upk2(lo, hi, acc[jb]);
        g_Pre[(b0 + bg * 4 + jb) * 2048 + og] = lo + hi + bias;
    }
}

// -------- K6: squash over D1=32 per (b, n1) --------
__global__ void k_squash(float* __restrict__ out) {
    int t = threadIdx.x;
    int gid = blockIdx.x * 8 + (t >> 5);
    int lane = t & 31;
    int b = gid >> 6;
    int n = gid & 63;
    int idx = b * 2048 + n * 32 + lane;
    float val = g_Pre[idx];
    float sq = val * val;
#pragma unroll
    for (int off = 16; off > 0; off >>= 1)
        sq += __shfl_xor_sync(0xffffffffu, sq, off);
    float norm = sqrtf(sq);
    float coef = 1.0f - 1.0f / (expf(norm) + 1e-20f);
    out[idx] = coef * val / (norm + 1e-20f);
}

extern "C" void kernel_launch(void* const* d_in, const int* in_sizes, int n_in,
                              void* d_out, int out_size) {
    const float* x1     = (const float*)d_in[0];
    const float* x2     = (const float*)d_in[1];
    const float* x3     = (const float*)d_in[2];
    const float* W      = (const float*)d_in[3];
    const float* conv_w = (const float*)d_in[4];
    const float* conv_b = (const float*)d_in[5];
    float* out = (float*)d_out;

    k_transposeW<<<4194304 / 256, 256>>>(W);
    k_prepA     <<<65536 / 256, 256>>>(conv_w);
    k_transform <<<dim3(16, 64), 128>>>(x1, x2, x3);
    k_rnorm     <<<131072 / 256, 256>>>();
    k_kv        <<<dim3(2, BB), 256>>>();
    k_xmid      <<<dim3(16, BB), 128>>>();
    k_conv      <<<dim3(4, 64), 256>>>(conv_b);
    k_squash    <<<1024, 256>>>(out);
}

// round 6
// speedup vs baseline: 1.2746x; 1.0282x over previous
#include <cuda_runtime.h>
#include <math.h>

typedef unsigned long long ull;

// Problem constants
#define BB   128
#define NN0  64      // positions (j / c / d)
#define DD0  32      // i
#define CC   2048    // channels kz = n1*32 + d1
#define KC   65

// -------- scratch (device globals) --------
__device__ float g_A [CC * DD0 * NN0];          // A'[o][ci][d]
__device__ float g_U1[BB * NN0 * CC];           // [b][j][kz]
__device__ float g_U2[BB * NN0 * CC];
__device__ float g_U3[BB * NN0 * CC];
__device__ float g_R1[BB * CC];
__device__ float g_R2[BB * CC];
__device__ float g_R3[BB * CC];
__device__ float g_Spart[BB * NN0 * 64];        // per-warp partials of s[b][j]
__device__ float g_KVh[4 * BB * NN0 * NN0];     // split-k kv partials [h][b][c][d]
__device__ float g_Xm[BB * CC * NN0];           // [b][kz][d]  (d contiguous)

// -------- f32x2 helpers --------
__device__ __forceinline__ ull pk2(float lo, float hi) {
    ull r; asm("mov.b64 %0, {%1, %2};" : "=l"(r) : "f"(lo), "f"(hi)); return r;
}
__device__ __forceinline__ void upk2(float& lo, float& hi, ull v) {
    asm("mov.b64 {%0, %1}, %2;" : "=f"(lo), "=f"(hi) : "l"(v));
}
__device__ __forceinline__ void fma2(ull& acc, ull a, ull b) {
    asm("fma.rn.f32x2 %0, %1, %2, %3;" : "=l"(acc) : "l"(a), "l"(b), "l"(acc));
}
__device__ __forceinline__ ull add2(ull a, ull b) {
    ull r; asm("add.rn.f32x2 %0, %1, %2;" : "=l"(r) : "l"(a), "l"(b)); return r;
}

__device__ __forceinline__ float focus_v(float u) {
    return fmaf(fmaxf(u, 0.0f), 0.2f, 2e-7f);   // (relu(u)+1e-6)/5
}

// -------- K0: A'[o][ci][d] = window-sum of conv_w + identity --------
__global__ void k_prepA(const float* __restrict__ cw) {
    int tid = blockIdx.x * 256 + threadIdx.x;   // 65536
    int o = tid >> 5, ci = tid & 31;
    const float* wr = cw + (o * 32 + ci) * 65;
    float id = (ci == (o & 31)) ? 1.0f : 0.0f;
    float* ar = g_A + (o * 32 + ci) * 64;
    float s = 0.f;
    for (int k = 0; k <= 32; k++) s += wr[k];
    ar[0] = s + id;
    for (int p = 1; p < 64; p++) {
        int addk = p + 32;
        if (addk <= 64) s += wr[addk];
        int rmk = p - 32;
        if (rmk >= 0) s -= wr[rmk];
        ar[p] = s + id;
    }
}

// -------- K1: transform, f32x2 paired over batch; W read directly (coalesced) --------
__global__ __launch_bounds__(128) void k_transform(
    const float* __restrict__ x1, const float* __restrict__ x2, const float* __restrict__ x3,
    const float* __restrict__ W)
{
    __shared__ __align__(16) ull xs[3][64][32];   // b-pairs, 48KB
    int t  = threadIdx.x;
    int j  = blockIdx.y;
    int kz = blockIdx.x * 128 + t;

    for (int e = t; e < 64 * 32; e += 128) {
        int bp = e >> 5, i = e & 31;
        int s0 = (2 * bp) * 2048 + j * 32 + i, s1 = s0 + 2048;
        xs[0][bp][i] = pk2(x1[s0], x1[s1]);
        xs[1][bp][i] = pk2(x2[s0], x2[s1]);
        xs[2][bp][i] = pk2(x3[s0], x3[s1]);
    }

    // W[k][j][i][z], kz = k*32+z : lane==z -> 128B coalesced per warp
    ull w2[32];
    int wbase = (kz >> 5) * 65536 + j * 1024 + (kz & 31);
#pragma unroll
    for (int i = 0; i < 32; i++) { float w = W[wbase + i * 32]; w2[i] = pk2(w, w); }

    __syncthreads();

    for (int bp = 0; bp < 64; bp++) {
        ull a1 = 0ULL, a2 = 0ULL, a3 = 0ULL;
        const ulonglong2* p0 = (const ulonglong2*)xs[0][bp];
        const ulonglong2* p1 = (const ulonglong2*)xs[1][bp];
        const ulonglong2* p2 = (const ulonglong2*)xs[2][bp];
#pragma unroll
        for (int q = 0; q < 16; q++) {
            ulonglong2 v0 = p0[q], v1 = p1[q], v2 = p2[q];
            fma2(a1, w2[2 * q], v0.x); fma2(a1, w2[2 * q + 1], v0.y);
            fma2(a2, w2[2 * q], v1.x); fma2(a2, w2[2 * q + 1], v1.y);
            fma2(a3, w2[2 * q], v2.x); fma2(a3, w2[2 * q + 1], v2.y);
        }
        float lo, hi;
        int o0 = (2 * bp) * 131072 + j * 2048 + kz, o1 = o0 + 131072;
        upk2(lo, hi, a1); g_U1[o0] = lo; g_U1[o1] = hi;
        upk2(lo, hi, a2); g_U2[o0] = lo; g_U2[o1] = hi;
        upk2(lo, hi, a3); g_U3[o0] = lo; g_U3[o1] = hi;
    }
}

// -------- K2: focus ratios r = ||v||/||v^3||, 1 kz/thread, + s[b][j] warp partials --------
__global__ __launch_bounds__(256) void k_rnorm() {
    int tid = blockIdx.x * 256 + threadIdx.x;   // 262144 threads
    int b  = tid >> 11;
    int kz = tid & 2047;
    int base = b * 131072 + kz;
    int lane = threadIdx.x & 31;
    int widx = (kz >> 5);                        // 64 warps per b

    float s2a = 0.f, s6a = 0.f, s2b = 0.f, s6b = 0.f, s2c = 0.f, s6c = 0.f;
    for (int j = 0; j < 64; j++) {
        int idx = base + j * 2048;
        float v1 = focus_v(g_U1[idx]);
        float v2 = focus_v(g_U2[idx]);
        float v3 = focus_v(g_U3[idx]);
        float q1 = v1 * v1, c1 = q1 * v1; s2a += q1; s6a = fmaf(c1, c1, s6a);
        float q2 = v2 * v2, c2 = q2 * v2; s2b += q2; s6b = fmaf(c2, c2, s6b);
        float q3 = v3 * v3, c3 = q3 * v3; s2c += q3; s6c = fmaf(c3, c3, s6c);
    }
    float r1 = sqrtf(s2a) * rsqrtf(s6a);
    float r2 = sqrtf(s2b) * rsqrtf(s6b);
    float r3 = sqrtf(s2c) * rsqrtf(s6c);
    g_R1[tid] = r1;
    g_R2[tid] = r2;
    g_R3[tid] = r3;

    // s[b][j] = sum_kz r1 * v1^3 : warp partials over 32 kz
    for (int j = 0; j < 64; j++) {
        float v = focus_v(g_U1[base + j * 2048]);
        float f = r1 * v * v * v;
#pragma unroll
        for (int off = 16; off > 0; off >>= 1)
            f += __shfl_xor_sync(0xffffffffu, f, off);
        if (lane == 0) g_Spart[b * 4096 + j * 64 + widx] = f;
    }
}

// -------- K3: kv split over 4 channel quarters, f32x2 paired over d --------
__global__ __launch_bounds__(256) void k_kv() {
    __shared__ __align__(16) float As2[64 * 68];    // [kk][c]
    __shared__ __align__(16) float Bs2[64 * 68];
    __shared__ float Rs2[512], Rs3[512];
    int h = blockIdx.x, b = blockIdx.y;
    int t = threadIdx.x;
    int c0 = (t & 15) * 4, d0 = (t >> 4) * 4;
    int kzbase = h * 512;

    for (int e = t; e < 512; e += 256) {
        Rs2[e] = g_R2[b * 2048 + kzbase + e];
        Rs3[e] = g_R3[b * 2048 + kzbase + e];
    }
    __syncthreads();

    ull acc[4][2];
#pragma unroll
    for (int i = 0; i < 4; i++) { acc[i][0] = 0ULL; acc[i][1] = 0ULL; }

    for (int s = 0; s < 8; s++) {
        int kz0 = kzbase + s * 64;
        for (int e = t; e < 4096; e += 256) {
            int c = e >> 6, kk = e & 63;
            int kz = kz0 + kk;
            float v2 = focus_v(g_U2[b * 131072 + c * 2048 + kz]);
            float v3 = focus_v(g_U3[b * 131072 + c * 2048 + kz]);
            As2[kk * 68 + c] = Rs2[s * 64 + kk] * v2 * v2 * v2;
            Bs2[kk * 68 + c] = Rs3[s * 64 + kk] * v3 * v3 * v3;
        }
        __syncthreads();
#pragma unroll
        for (int kk = 0; kk < 64; kk++) {
            float4 av = *(const float4*)&As2[kk * 68 + c0];
            ulonglong2 bv = *(const ulonglong2*)&Bs2[kk * 68 + d0];
            ull a0 = pk2(av.x, av.x), a1 = pk2(av.y, av.y);
            ull a2 = pk2(av.z, av.z), a3 = pk2(av.w, av.w);
            fma2(acc[0][0], a0, bv.x); fma2(acc[0][1], a0, bv.y);
            fma2(acc[1][0], a1, bv.x); fma2(acc[1][1], a1, bv.y);
            fma2(acc[2][0], a2, bv.x); fma2(acc[2][1], a2, bv.y);
            fma2(acc[3][0], a3, bv.x); fma2(acc[3][1], a3, bv.y);
        }
        __syncthreads();
    }
#pragma unroll
    for (int i = 0; i < 4; i++) {
        float l0, h0v, l1, h1v;
        upk2(l0, h0v, acc[i][0]);
        upk2(l1, h1v, acc[i][1]);
        int obase = (h * 128 + b) * 4096 + (c0 + i) * 64 + d0;
        g_KVh[obase + 0] = l0; g_KVh[obase + 1] = h0v;
        g_KVh[obase + 2] = l1; g_KVh[obase + 3] = h1v;
    }
}

// -------- K4: xmid with fused z; output [b][kz][d] via smem transpose --------
__global__ __launch_bounds__(128) void k_xmid() {
    __shared__ __align__(16) ull kvs2[2048];        // kv[c][d-pairs], 16KB
    __shared__ float ss[64];
    __shared__ float stage[64 * 65];    // half-tile transpose staging
    int b = blockIdx.y;
    int t = threadIdx.x;
    int kz = blockIdx.x * 128 + t;

    for (int e = t; e < 2048; e += 128) {
        ull p0 = ((const ull*)g_KVh)[b * 2048 + e];
        ull p1 = ((const ull*)g_KVh)[(128 + b) * 2048 + e];
        ull p2 = ((const ull*)g_KVh)[(256 + b) * 2048 + e];
        ull p3 = ((const ull*)g_KVh)[(384 + b) * 2048 + e];
        kvs2[e] = add2(add2(p0, p1), add2(p2, p3));
    }
    if (t < 64) {
        float s = 0.f;
        const float* sp = &g_Spart[b * 4096 + t * 64];
        for (int w = 0; w < 64; w++) s += sp[w];
        ss[t] = s;
    }
    __syncthreads();

    ull xr[32];
#pragma unroll
    for (int d = 0; d < 32; d++) xr[d] = 0ULL;

    float r1 = g_R1[b * 2048 + kz];
    float zacc = 0.f;
    for (int c = 0; c < 64; c++) {
        float v = focus_v(g_U1[b * 131072 + c * 2048 + kz]);
        float f = r1 * v * v * v;
        zacc = fmaf(f, ss[c], zacc);
        ull f2v = pk2(f, f);
        const ulonglong2* kp = (const ulonglong2*)&kvs2[c * 32];
#pragma unroll
        for (int d8 = 0; d8 < 16; d8++) {
            ulonglong2 kq = kp[d8];
            fma2(xr[2 * d8],     f2v, kq.x);
            fma2(xr[2 * d8 + 1], f2v, kq.y);
        }
    }
    float z = 1.0f / (zacc + 1.1920929e-07f);

#pragma unroll
    for (int half = 0; half < 2; half++) {
        if ((t >> 6) == half) {
            int row = t & 63;
#pragma unroll
            for (int d2 = 0; d2 < 32; d2++) {
                float lo, hi; upk2(lo, hi, xr[d2]);
                stage[row * 65 + 2 * d2]     = lo * z;
                stage[row * 65 + 2 * d2 + 1] = hi * z;
            }
        }
        __syncthreads();
        for (int e = t; e < 4096; e += 128) {
            int kzi = e >> 6, d = e & 63;
            g_Xm[b * 131072 + (blockIdx.x * 128 + half * 64 + kzi) * 64 + d] = stage[kzi * 65 + d];
        }
        __syncthreads();
    }
}

// -------- K5: conv-as-GEMM with A' + fused squash --------
// pre[b][o] = sum_{ci,d} A'[o,ci,d]*x[b,(g,ci),d] + 64*bias ; then squash over o (warp)
__global__ __launch_bounds__(256) void k_convsq(const float* __restrict__ conv_b,
                                                float* __restrict__ out) {
    __shared__ __align__(16) float As[32 * 68];   // [ol][d]
    __shared__ __align__(16) float Xs[32 * 68];   // [bb][d]
    int t  = threadIdx.x;
    int o  = t & 31;
    int bg = t >> 5;             // warp id; lanes within warp = o
    int b0 = blockIdx.x * 32;
    int g  = blockIdx.y;

    ull acc[4] = {0ULL, 0ULL, 0ULL, 0ULL};

    for (int ci = 0; ci < 32; ci++) {
        for (int e = t; e < 2048; e += 256) {
            int ol = e >> 6, d = e & 63;
            As[ol * 68 + d] = g_A[((g * 32 + ol) * 32 + ci) * 64 + d];
            Xs[ol * 68 + d] = g_Xm[(b0 + ol) * 131072 + (g * 32 + ci) * 64 + d];
        }
        __syncthreads();
        const ulonglong2* ap = (const ulonglong2*)&As[o * 68];
#pragma unroll
        for (int k8 = 0; k8 < 16; k8++) {
            ulonglong2 av = ap[k8];
#pragma unroll
            for (int jb = 0; jb < 4; jb++) {
                ulonglong2 xv = *(const ulonglong2*)&Xs[(bg * 4 + jb) * 68 + k8 * 4];
                fma2(acc[jb], av.x, xv.x);
                fma2(acc[jb], av.y, xv.y);
            }
        }
        __syncthreads();
    }

    int og = g * 32 + o;
    float bias = 64.0f * conv_b[og];
#pragma unroll
    for (int jb = 0; jb < 4; jb++) {
        float lo, hi; upk2(lo, hi, acc[jb]);
        float val = lo + hi + bias;
        // squash: norm over the 32 o-lanes (one capsule, one batch)
        float sq = val * val;
#pragma unroll
        for (int off = 16; off > 0; off >>= 1)
            sq += __shfl_xor_sync(0xffffffffu, sq, off);
        float norm = sqrtf(sq);
        float coef = 1.0f - 1.0f / (expf(norm) + 1e-20f);
        out[(b0 + bg * 4 + jb) * 2048 + og] = coef * val / (norm + 1e-20f);
    }
}

extern "C" void kernel_launch(void* const* d_in, const int* in_sizes, int n_in,
                              void* d_out, int out_size) {
    const float* x1     = (const float*)d_in[0];
    const float* x2     = (const float*)d_in[1];
    const float* x3     = (const float*)d_in[2];
    const float* W      = (const float*)d_in[3];
    const float* conv_w = (const float*)d_in[4];
    const float* conv_b = (const float*)d_in[5];
    float* out = (float*)d_out;

    k_prepA    <<<65536 / 256, 256>>>(conv_w);
    k_transform<<<dim3(16, 64), 128>>>(x1, x2, x3, W);
    k_rnorm    <<<262144 / 256, 256>>>();
    k_kv       <<<dim3(4, BB), 256>>>();
    k_xmid     <<<dim3(16, BB), 128>>>();
    k_convsq   <<<dim3(4, 64), 256>>>(conv_b, out);
}

// round 7
// speedup vs baseline: 1.3015x; 1.0211x over previous
#include <cuda_runtime.h>
#include <math.h>

typedef unsigned long long ull;

// Problem constants
#define BB   128
#define NN0  64      // positions (j / c / d)
#define DD0  32      // i
#define CC   2048    // channels kz = n1*32 + d1
#define KC   65

// -------- scratch (device globals) --------
__device__ float g_A [CC * DD0 * NN0];          // A'[o][ci][d]
__device__ float g_U1[BB * NN0 * CC];           // [b][j][kz]
__device__ float g_U2[BB * NN0 * CC];
__device__ float g_U3[BB * NN0 * CC];
__device__ float g_R1[BB * CC];
__device__ float g_R2[BB * CC];
__device__ float g_R3[BB * CC];
__device__ float g_Spart[BB * NN0 * 64];        // per-warp partials of s[b][j]
__device__ float g_KVh[4 * BB * NN0 * NN0];     // split-k kv partials [h][b][c][d]
__device__ float g_Xm[BB * CC * NN0];           // [b][kz][d]  (d contiguous)

// -------- f32x2 helpers --------
__device__ __forceinline__ ull pk2(float lo, float hi) {
    ull r; asm("mov.b64 %0, {%1, %2};" : "=l"(r) : "f"(lo), "f"(hi)); return r;
}
__device__ __forceinline__ void upk2(float& lo, float& hi, ull v) {
    asm("mov.b64 {%0, %1}, %2;" : "=f"(lo), "=f"(hi) : "l"(v));
}
__device__ __forceinline__ void fma2(ull& acc, ull a, ull b) {
    asm("fma.rn.f32x2 %0, %1, %2, %3;" : "=l"(acc) : "l"(a), "l"(b), "l"(acc));
}
__device__ __forceinline__ ull add2(ull a, ull b) {
    ull r; asm("add.rn.f32x2 %0, %1, %2;" : "=l"(r) : "l"(a), "l"(b)); return r;
}

__device__ __forceinline__ float focus_v(float u) {
    return fmaf(fmaxf(u, 0.0f), 0.2f, 2e-7f);   // (relu(u)+1e-6)/5
}

// -------- K0: A'[o][ci][d] = window-sum of conv_w + identity --------
__global__ void k_prepA(const float* __restrict__ cw) {
    int tid = blockIdx.x * 256 + threadIdx.x;   // 65536
    int o = tid >> 5, ci = tid & 31;
    const float* wr = cw + (o * 32 + ci) * 65;
    float id = (ci == (o & 31)) ? 1.0f : 0.0f;
    float* ar = g_A + (o * 32 + ci) * 64;
    float s = 0.f;
    for (int k = 0; k <= 32; k++) s += wr[k];
    ar[0] = s + id;
    for (int p = 1; p < 64; p++) {
        int addk = p + 32;
        if (addk <= 64) s += wr[addk];
        int rmk = p - 32;
        if (rmk >= 0) s -= wr[rmk];
        ar[p] = s + id;
    }
}

// -------- K1: transform, f32x2 paired over batch; W read directly (coalesced) --------
__global__ __launch_bounds__(128) void k_transform(
    const float* __restrict__ x1, const float* __restrict__ x2, const float* __restrict__ x3,
    const float* __restrict__ W)
{
    __shared__ __align__(16) ull xs[3][64][32];   // b-pairs, 48KB
    int t  = threadIdx.x;
    int j  = blockIdx.y;
    int kz = blockIdx.x * 128 + t;

    for (int e = t; e < 64 * 32; e += 128) {
        int bp = e >> 5, i = e & 31;
        int s0 = (2 * bp) * 2048 + j * 32 + i, s1 = s0 + 2048;
        xs[0][bp][i] = pk2(x1[s0], x1[s1]);
        xs[1][bp][i] = pk2(x2[s0], x2[s1]);
        xs[2][bp][i] = pk2(x3[s0], x3[s1]);
    }

    // W[k][j][i][z], kz = k*32+z : lane==z -> 128B coalesced per warp
    ull w2[32];
    int wbase = (kz >> 5) * 65536 + j * 1024 + (kz & 31);
#pragma unroll
    for (int i = 0; i < 32; i++) { float w = W[wbase + i * 32]; w2[i] = pk2(w, w); }

    __syncthreads();

    for (int bp = 0; bp < 64; bp++) {
        ull a1 = 0ULL, a2 = 0ULL, a3 = 0ULL;
        const ulonglong2* p0 = (const ulonglong2*)xs[0][bp];
        const ulonglong2* p1 = (const ulonglong2*)xs[1][bp];
        const ulonglong2* p2 = (const ulonglong2*)xs[2][bp];
#pragma unroll
        for (int q = 0; q < 16; q++) {
            ulonglong2 v0 = p0[q], v1 = p1[q], v2 = p2[q];
            fma2(a1, w2[2 * q], v0.x); fma2(a1, w2[2 * q + 1], v0.y);
            fma2(a2, w2[2 * q], v1.x); fma2(a2, w2[2 * q + 1], v1.y);
            fma2(a3, w2[2 * q], v2.x); fma2(a3, w2[2 * q + 1], v2.y);
        }
        float lo, hi;
        int o0 = (2 * bp) * 131072 + j * 2048 + kz, o1 = o0 + 131072;
        upk2(lo, hi, a1); g_U1[o0] = lo; g_U1[o1] = hi;
        upk2(lo, hi, a2); g_U2[o0] = lo; g_U2[o1] = hi;
        upk2(lo, hi, a3); g_U3[o0] = lo; g_U3[o1] = hi;
    }
}

// -------- K2: focus ratios r = ||v||/||v^3||, 1 kz/thread, + s[b][j] warp partials --------
__global__ __launch_bounds__(256) void k_rnorm() {
    int tid = blockIdx.x * 256 + threadIdx.x;   // 262144 threads
    int b  = tid >> 11;
    int kz = tid & 2047;
    int base = b * 131072 + kz;
    int lane = threadIdx.x & 31;
    int widx = (kz >> 5);                        // 64 warps per b

    float s2a = 0.f, s6a = 0.f, s2b = 0.f, s6b = 0.f, s2c = 0.f, s6c = 0.f;
    for (int j = 0; j < 64; j++) {
        int idx = base + j * 2048;
        float v1 = focus_v(g_U1[idx]);
        float v2 = focus_v(g_U2[idx]);
        float v3 = focus_v(g_U3[idx]);
        float q1 = v1 * v1, c1 = q1 * v1; s2a += q1; s6a = fmaf(c1, c1, s6a);
        float q2 = v2 * v2, c2 = q2 * v2; s2b += q2; s6b = fmaf(c2, c2, s6b);
        float q3 = v3 * v3, c3 = q3 * v3; s2c += q3; s6c = fmaf(c3, c3, s6c);
    }
    float r1 = sqrtf(s2a) * rsqrtf(s6a);
    float r2 = sqrtf(s2b) * rsqrtf(s6b);
    float r3 = sqrtf(s2c) * rsqrtf(s6c);
    g_R1[tid] = r1;
    g_R2[tid] = r2;
    g_R3[tid] = r3;

    // s[b][j] = sum_kz r1 * v1^3 : warp partials over 32 kz
    for (int j = 0; j < 64; j++) {
        float v = focus_v(g_U1[base + j * 2048]);
        float f = r1 * v * v * v;
#pragma unroll
        for (int off = 16; off > 0; off >>= 1)
            f += __shfl_xor_sync(0xffffffffu, f, off);
        if (lane == 0) g_Spart[b * 4096 + j * 64 + widx] = f;
    }
}

// -------- K3: kv split over 4 channel quarters; 8x4 register tile, f32x2 over d --------
__global__ __launch_bounds__(128) void k_kv() {
    __shared__ __align__(16) float As2[64 * 68];    // [kk][c]
    __shared__ __align__(16) float Bs2[64 * 68];    // [kk][d]
    __shared__ float Rs2[512], Rs3[512];
    int h = blockIdx.x, b = blockIdx.y;
    int t = threadIdx.x;
    int c0 = (t >> 4) * 8;      // 8 groups of 8 c
    int d0 = (t & 15) * 4;      // 16 groups of 4 d
    int kzbase = h * 512;

    for (int e = t; e < 512; e += 128) {
        Rs2[e] = g_R2[b * 2048 + kzbase + e];
        Rs3[e] = g_R3[b * 2048 + kzbase + e];
    }
    __syncthreads();

    ull acc[8][2];
#pragma unroll
    for (int i = 0; i < 8; i++) { acc[i][0] = 0ULL; acc[i][1] = 0ULL; }

    for (int s = 0; s < 8; s++) {
        int kz0 = kzbase + s * 64;
        for (int e = t; e < 4096; e += 128) {
            int c = e >> 6, kk = e & 63;
            int kz = kz0 + kk;
            float v2 = focus_v(g_U2[b * 131072 + c * 2048 + kz]);
            float v3 = focus_v(g_U3[b * 131072 + c * 2048 + kz]);
            As2[kk * 68 + c] = Rs2[s * 64 + kk] * v2 * v2 * v2;
            Bs2[kk * 68 + c] = Rs3[s * 64 + kk] * v3 * v3 * v3;
        }
        __syncthreads();
#pragma unroll 8
        for (int kk = 0; kk < 64; kk++) {
            float4 av0 = *(const float4*)&As2[kk * 68 + c0];
            float4 av1 = *(const float4*)&As2[kk * 68 + c0 + 4];
            ulonglong2 bv = *(const ulonglong2*)&Bs2[kk * 68 + d0];
            ull a0 = pk2(av0.x, av0.x), a1 = pk2(av0.y, av0.y);
            ull a2 = pk2(av0.z, av0.z), a3 = pk2(av0.w, av0.w);
            ull a4 = pk2(av1.x, av1.x), a5 = pk2(av1.y, av1.y);
            ull a6 = pk2(av1.z, av1.z), a7 = pk2(av1.w, av1.w);
            fma2(acc[0][0], a0, bv.x); fma2(acc[0][1], a0, bv.y);
            fma2(acc[1][0], a1, bv.x); fma2(acc[1][1], a1, bv.y);
            fma2(acc[2][0], a2, bv.x); fma2(acc[2][1], a2, bv.y);
            fma2(acc[3][0], a3, bv.x); fma2(acc[3][1], a3, bv.y);
            fma2(acc[4][0], a4, bv.x); fma2(acc[4][1], a4, bv.y);
            fma2(acc[5][0], a5, bv.x); fma2(acc[5][1], a5, bv.y);
            fma2(acc[6][0], a6, bv.x); fma2(acc[6][1], a6, bv.y);
            fma2(acc[7][0], a7, bv.x); fma2(acc[7][1], a7, bv.y);
        }
        __syncthreads();
    }
#pragma unroll
    for (int i = 0; i < 8; i++) {
        float l0, h0v, l1, h1v;
        upk2(l0, h0v, acc[i][0]);
        upk2(l1, h1v, acc[i][1]);
        int obase = (h * 128 + b) * 4096 + (c0 + i) * 64 + d0;
        g_KVh[obase + 0] = l0; g_KVh[obase + 1] = h0v;
        g_KVh[obase + 2] = l1; g_KVh[obase + 3] = h1v;
    }
}

// -------- K4: xmid with fused z; output [b][kz][d] via smem transpose --------
__global__ __launch_bounds__(128) void k_xmid() {
    __shared__ __align__(16) ull kvs2[2048];        // kv[c][d-pairs], 16KB
    __shared__ float ss[64];
    __shared__ float stage[64 * 65];    // half-tile transpose staging
    int b = blockIdx.y;
    int t = threadIdx.x;
    int kz = blockIdx.x * 128 + t;

    for (int e = t; e < 2048; e += 128) {
        ull p0 = ((const ull*)g_KVh)[b * 2048 + e];
        ull p1 = ((const ull*)g_KVh)[(128 + b) * 2048 + e];
        ull p2 = ((const ull*)g_KVh)[(256 + b) * 2048 + e];
        ull p3 = ((const ull*)g_KVh)[(384 + b) * 2048 + e];
        kvs2[e] = add2(add2(p0, p1), add2(p2, p3));
    }
    if (t < 64) {
        float s = 0.f;
        const float* sp = &g_Spart[b * 4096 + t * 64];
        for (int w = 0; w < 64; w++) s += sp[w];
        ss[t] = s;
    }
    __syncthreads();

    ull xr[32];
#pragma unroll
    for (int d = 0; d < 32; d++) xr[d] = 0ULL;

    float r1 = g_R1[b * 2048 + kz];
    float zacc = 0.f;
    for (int c = 0; c < 64; c++) {
        float v = focus_v(g_U1[b * 131072 + c * 2048 + kz]);
        float f = r1 * v * v * v;
        zacc = fmaf(f, ss[c], zacc);
        ull f2v = pk2(f, f);
        const ulonglong2* kp = (const ulonglong2*)&kvs2[c * 32];
#pragma unroll
        for (int d8 = 0; d8 < 16; d8++) {
            ulonglong2 kq = kp[d8];
            fma2(xr[2 * d8],     f2v, kq.x);
            fma2(xr[2 * d8 + 1], f2v, kq.y);
        }
    }
    float z = 1.0f / (zacc + 1.1920929e-07f);

#pragma unroll
    for (int half = 0; half < 2; half++) {
        if ((t >> 6) == half) {
            int row = t & 63;
#pragma unroll
            for (int d2 = 0; d2 < 32; d2++) {
                float lo, hi; upk2(lo, hi, xr[d2]);
                stage[row * 65 + 2 * d2]     = lo * z;
                stage[row * 65 + 2 * d2 + 1] = hi * z;
            }
        }
        __syncthreads();
        for (int e = t; e < 4096; e += 128) {
            int kzi = e >> 6, d = e & 63;
            g_Xm[b * 131072 + (blockIdx.x * 128 + half * 64 + kzi) * 64 + d] = stage[kzi * 65 + d];
        }
        __syncthreads();
    }
}

// -------- K5: conv-as-GEMM with A' + fused squash --------
__global__ __launch_bounds__(256) void k_convsq(const float* __restrict__ conv_b,
                                                float* __restrict__ out) {
    __shared__ __align__(16) float As[32 * 68];   // [ol][d]
    __shared__ __align__(16) float Xs[32 * 68];   // [bb][d]
    int t  = threadIdx.x;
    int o  = t & 31;
    int bg = t >> 5;
    int b0 = blockIdx.x * 32;
    int g  = blockIdx.y;

    ull acc[4] = {0ULL, 0ULL, 0ULL, 0ULL};

    for (int ci = 0; ci < 32; ci++) {
        for (int e = t; e < 2048; e += 256) {
            int ol = e >> 6, d = e & 63;
            As[ol * 68 + d] = g_A[((g * 32 + ol) * 32 + ci) * 64 + d];
            Xs[ol * 68 + d] = g_Xm[(b0 + ol) * 131072 + (g * 32 + ci) * 64 + d];
        }
        __syncthreads();
        const ulonglong2* ap = (const ulonglong2*)&As[o * 68];
#pragma unroll
        for (int k8 = 0; k8 < 16; k8++) {
            ulonglong2 av = ap[k8];
#pragma unroll
            for (int jb = 0; jb < 4; jb++) {
                ulonglong2 xv = *(const ulonglong2*)&Xs[(bg * 4 + jb) * 68 + k8 * 4];
                fma2(acc[jb], av.x, xv.x);
                fma2(acc[jb], av.y, xv.y);
            }
        }
        __syncthreads();
    }

    int og = g * 32 + o;
    float bias = 64.0f * conv_b[og];
#pragma unroll
    for (int jb = 0; jb < 4; jb++) {
        float lo, hi; upk2(lo, hi, acc[jb]);
        float val = lo + hi + bias;
        float sq = val * val;
#pragma unroll
        for (int off = 16; off > 0; off >>= 1)
            sq += __shfl_xor_sync(0xffffffffu, sq, off);
        float norm = sqrtf(sq);
        float coef = 1.0f - 1.0f / (expf(norm) + 1e-20f);
        out[(b0 + bg * 4 + jb) * 2048 + og] = coef * val / (norm + 1e-20f);
    }
}

extern "C" void kernel_launch(void* const* d_in, const int* in_sizes, int n_in,
                              void* d_out, int out_size) {
    const float* x1     = (const float*)d_in[0];
    const float* x2     = (const float*)d_in[1];
    const float* x3     = (const float*)d_in[2];
    const float* W      = (const float*)d_in[3];
    const float* conv_w = (const float*)d_in[4];
    const float* conv_b = (const float*)d_in[5];
    float* out = (float*)d_out;

    k_prepA    <<<65536 / 256, 256>>>(conv_w);
    k_transform<<<dim3(16, 64), 128>>>(x1, x2, x3, W);
    k_rnorm    <<<262144 / 256, 256>>>();
    k_kv       <<<dim3(4, BB), 128>>>();
    k_xmid     <<<dim3(16, BB), 128>>>();
    k_convsq   <<<dim3(4, 64), 256>>>(conv_b, out);
}